// round 3
// baseline (speedup 1.0000x reference)
#include <cuda_runtime.h>
#include <cstdint>

// Problem constants (fixed by setup_inputs)
#define S_LEN   2048
#define HID     2048
#define EMBD    512
#define VOCAB_L 32000LL
#define EOS_ID  2LL
#define NEMB    4

// GEMM tiling
#define BM 128
#define BN 128
#define BK 16
#define NTHREADS 256

// dtype flag for input_ids: 1 = int64 little-endian, 0 = int32
__device__ int g_ids_is64;

// ---------- f32x2 packed-FMA helpers (Blackwell FFMA2) ----------
__device__ __forceinline__ unsigned long long pack2(float x, float y) {
    unsigned long long r;
    asm("mov.b64 %0, {%1, %2};" : "=l"(r)
        : "r"(__float_as_uint(x)), "r"(__float_as_uint(y)));
    return r;
}
__device__ __forceinline__ unsigned long long fma2(unsigned long long a,
                                                   unsigned long long b,
                                                   unsigned long long c) {
    unsigned long long d;
    asm("fma.rn.f32x2 %0, %1, %2, %3;" : "=l"(d) : "l"(a), "l"(b), "l"(c));
    return d;
}
__device__ __forceinline__ float2 unpack2(unsigned long long v) {
    unsigned lo, hi;
    asm("mov.b64 {%0, %1}, %2;" : "=r"(lo), "=r"(hi) : "l"(v));
    float2 f;
    f.x = __uint_as_float(lo);
    f.y = __uint_as_float(hi);
    return f;
}

// Detect whether the ids buffer holds int64 (odd int32 words all zero,
// guaranteed because token ids < 32000) or int32. Reading the first 128
// int32 words is in-bounds under both interpretations (>=8192 elements).
__global__ void detect_ids_dtype_kernel(const int* __restrict__ ids32) {
    if (threadIdx.x == 0) {
        int nz = 0;
#pragma unroll
        for (int i = 1; i < 128; i += 2) nz |= ids32[i];
        g_ids_is64 = (nz == 0) ? 1 : 0;
    }
}

__device__ __forceinline__ long long load_id(const void* __restrict__ ids,
                                             int i, int is64) {
    if (is64) return ((const long long*)ids)[i];
    return (long long)((const int*)ids)[i];
}

__global__ __launch_bounds__(NTHREADS, 2)
void ngram_emb_kernel(const void* __restrict__ ids,
                      const float* __restrict__ word,
                      const float* __restrict__ e0, const float* __restrict__ e1,
                      const float* __restrict__ e2, const float* __restrict__ e3,
                      const float* __restrict__ p0, const float* __restrict__ p1,
                      const float* __restrict__ p2, const float* __restrict__ p3,
                      float* __restrict__ out)
{
    __shared__ float As[BK][BM + 4];   // 132-float rows: 528B, 16B-aligned rows
    __shared__ float Bs[BK][BN + 4];
    __shared__ int   s_newid[NEMB][BM];
    __shared__ int   s_rowid[BM];

    const int tid = threadIdx.x;
    const int m0  = blockIdx.y * BM;
    const int n0  = blockIdx.x * BN;

    const float* embs[NEMB]  = {e0, e1, e2, e3};
    const float* projs[NEMB] = {p0, p1, p2, p3};

    // ---- per-row hashed indices (segment logic reduces to <=2 lookbacks) ----
    if (tid < BM) {
        const int is64 = g_ids_is64;
        const int p = m0 + tid;
        const int t = p & (S_LEN - 1);           // position within sequence
        const long long id    = load_id(ids, p, is64);
        const long long prev1 = (t >= 1) ? load_id(ids, p - 1, is64) : EOS_ID;
        const long long prev2 = (t >= 2) ? load_id(ids, p - 2, is64) : EOS_ID;
        const bool ok1 = (t >= 1) && (prev1 != EOS_ID);
        const bool ok2 = (t >= 2) && (prev1 != EOS_ID) && (prev2 != EOS_ID);
        const long long s1 = ok1 ? prev1 : 0;
        const long long s2 = ok2 ? prev2 : 0;
        s_rowid[tid] = (int)id;
#pragma unroll
        for (int e = 0; e < NEMB; e++) {
            const long long dim = 128000LL + 2 * e + 1;
            const long long m1  = VOCAB_L % dim;            // = 32000 (dim > vocab)
            long long ng = id + s1 * m1;
            if (e >= 2) {
                const long long m2 = (m1 * VOCAB_L) % dim;  // vocab^2 mod dim
                ng += s2 * m2;
            }
            s_newid[e][tid] = (int)(ng % dim);
        }
    }
    __syncthreads();

    // ---- thread mapping: 16x16 threads, each 8x8 outputs ----
    const int tx = tid & 15;       // N direction
    const int ty = tid >> 4;       // M direction

    // loader mapping: 512 float4 per (128x16) tile, 2 per thread
    const int lrow = tid >> 2;     // 0..63  (also lrow+64)
    const int lc4  = tid & 3;      // which float4 in the 16-wide K slab

    unsigned long long acc[8][4];
#pragma unroll
    for (int i = 0; i < 8; i++)
#pragma unroll
        for (int j = 0; j < 4; j++) acc[i][j] = 0ull;

#pragma unroll
    for (int e = 0; e < NEMB; e++) {
        const float* __restrict__ emb  = embs[e];
        const float* __restrict__ proj = projs[e];
        const size_t arow0 = (size_t)s_newid[e][lrow]      * EMBD;
        const size_t arow1 = (size_t)s_newid[e][lrow + 64] * EMBD;
        const size_t brow0 = (size_t)(n0 + lrow)      * EMBD;
        const size_t brow1 = (size_t)(n0 + lrow + 64) * EMBD;

        for (int k0 = 0; k0 < EMBD; k0 += BK) {
            const int kc = k0 + lc4 * 4;
            const float4 a0 = *(const float4*)(emb  + arow0 + kc);
            const float4 a1 = *(const float4*)(emb  + arow1 + kc);
            const float4 b0 = *(const float4*)(proj + brow0 + kc);
            const float4 b1 = *(const float4*)(proj + brow1 + kc);

            __syncthreads();   // previous tile fully consumed
            const int kk = lc4 * 4;
            As[kk + 0][lrow] = a0.x; As[kk + 1][lrow] = a0.y;
            As[kk + 2][lrow] = a0.z; As[kk + 3][lrow] = a0.w;
            As[kk + 0][lrow + 64] = a1.x; As[kk + 1][lrow + 64] = a1.y;
            As[kk + 2][lrow + 64] = a1.z; As[kk + 3][lrow + 64] = a1.w;
            Bs[kk + 0][lrow] = b0.x; Bs[kk + 1][lrow] = b0.y;
            Bs[kk + 2][lrow] = b0.z; Bs[kk + 3][lrow] = b0.w;
            Bs[kk + 0][lrow + 64] = b1.x; Bs[kk + 1][lrow + 64] = b1.y;
            Bs[kk + 2][lrow + 64] = b1.z; Bs[kk + 3][lrow + 64] = b1.w;
            __syncthreads();

#pragma unroll
            for (int k = 0; k < BK; k++) {
                const float4 av0 = *(const float4*)&As[k][ty * 8];
                const float4 av1 = *(const float4*)&As[k][ty * 8 + 4];
                const float4 bv0 = *(const float4*)&Bs[k][tx * 8];
                const float4 bv1 = *(const float4*)&Bs[k][tx * 8 + 4];
                unsigned long long bp[4];
                bp[0] = pack2(bv0.x, bv0.y);
                bp[1] = pack2(bv0.z, bv0.w);
                bp[2] = pack2(bv1.x, bv1.y);
                bp[3] = pack2(bv1.z, bv1.w);
                const float av[8] = {av0.x, av0.y, av0.z, av0.w,
                                     av1.x, av1.y, av1.z, av1.w};
#pragma unroll
                for (int i = 0; i < 8; i++) {
                    const unsigned long long ap = pack2(av[i], av[i]);
#pragma unroll
                    for (int j = 0; j < 4; j++)
                        acc[i][j] = fma2(ap, bp[j], acc[i][j]);
                }
            }
        }
    }

    // ---- epilogue: add gathered word embedding, scale by 1/5 ----
    const float inv = 1.0f / 5.0f;
#pragma unroll
    for (int i = 0; i < 8; i++) {
        const int   mi   = ty * 8 + i;
        const size_t wro = (size_t)s_rowid[mi] * HID + n0 + tx * 8;
        const float4 w0  = *(const float4*)(word + wro);
        const float4 w1  = *(const float4*)(word + wro + 4);
        const float2 c0  = unpack2(acc[i][0]);
        const float2 c1  = unpack2(acc[i][1]);
        const float2 c2  = unpack2(acc[i][2]);
        const float2 c3  = unpack2(acc[i][3]);
        float4 r0, r1;
        r0.x = (w0.x + c0.x) * inv; r0.y = (w0.y + c0.y) * inv;
        r0.z = (w0.z + c1.x) * inv; r0.w = (w0.w + c1.y) * inv;
        r1.x = (w1.x + c2.x) * inv; r1.y = (w1.y + c2.y) * inv;
        r1.z = (w1.z + c3.x) * inv; r1.w = (w1.w + c3.y) * inv;
        float* op = out + (size_t)(m0 + mi) * HID + n0 + tx * 8;
        *(float4*)op       = r0;
        *(float4*)(op + 4) = r1;
    }
}

extern "C" void kernel_launch(void* const* d_in, const int* in_sizes, int n_in,
                              void* d_out, int out_size)
{
    // Identify inputs by element count (robust to metadata ordering):
    //   ids: 8192 (int32 or int64 -- auto-detected on device)
    //   word_emb: 32000*2048 = 65,536,000
    //   emb_e: (128001+2e)*512 = 65,536,512 + 1024*e
    //   proj_e: 2048*512 = 1,048,576 each, in appearance order
    const void* ids = nullptr;
    const float* word = nullptr;
    const float* emb[NEMB]  = {nullptr, nullptr, nullptr, nullptr};
    const float* proj[NEMB] = {nullptr, nullptr, nullptr, nullptr};
    int np = 0;
    int M = 8192;

    for (int i = 0; i < n_in; i++) {
        const long long sz = in_sizes[i];
        if (sz < 1000000) {                       // input_ids
            ids = d_in[i];
            M = (int)sz;
        } else if (sz == 65536000LL) {
            word = (const float*)d_in[i];
        } else if (sz == 65536512LL) {
            emb[0] = (const float*)d_in[i];
        } else if (sz == 65537536LL) {
            emb[1] = (const float*)d_in[i];
        } else if (sz == 65538560LL) {
            emb[2] = (const float*)d_in[i];
        } else if (sz == 65539584LL) {
            emb[3] = (const float*)d_in[i];
        } else if (sz == 1048576LL && np < NEMB) {
            proj[np++] = (const float*)d_in[i];
        }
    }

    detect_ids_dtype_kernel<<<1, 32>>>((const int*)ids);

    dim3 grid(HID / BN, M / BM);   // (16, 64)
    ngram_emb_kernel<<<grid, NTHREADS>>>(
        ids, word,
        emb[0], emb[1], emb[2], emb[3],
        proj[0], proj[1], proj[2], proj[3],
        (float*)d_out);
}

// round 5
// speedup vs baseline: 1.7707x; 1.7707x over previous
#include <cuda_runtime.h>
#include <cstdint>

// Problem constants
#define S_LEN   2048
#define HID     2048
#define EMBD    512
#define VOCAB_L 32000LL
#define EOS_ID  2LL
#define NEMB    4

// GEMM tiling
#define BM 128
#define BN 256
#define BK 32
#define NCHUNK 64                  // NEMB*EMBD/BK
#define A_F (BK * BM)              // 4096 floats per A stage
#define B_F (BK * BN)              // 8192 floats per B stage
#define NID_OFF (2 * A_F + 2 * B_F)
#define SMEM_BYTES ((NID_OFF + 512) * 4 + 512 * 4)

__device__ int g_ids_is64;

__device__ __forceinline__ uint32_t cvt_tf32(float x) {
    uint32_t u;
    asm("cvt.rna.tf32.f32 %0, %1;" : "=r"(u) : "f"(x));
    return u;
}

__device__ __forceinline__ void mma_tf32(float* d, const uint32_t* a,
                                         const uint32_t* b) {
    asm volatile(
        "mma.sync.aligned.m16n8k8.row.col.f32.tf32.tf32.f32 "
        "{%0,%1,%2,%3}, {%4,%5,%6,%7}, {%8,%9}, {%0,%1,%2,%3};"
        : "+f"(d[0]), "+f"(d[1]), "+f"(d[2]), "+f"(d[3])
        : "r"(a[0]), "r"(a[1]), "r"(a[2]), "r"(a[3]), "r"(b[0]), "r"(b[1]));
}

// Detect int64 vs int32 ids transport (odd words all zero => int64 LE, ids<32000)
__global__ void detect_ids_dtype_kernel(const int* __restrict__ ids32) {
    if (threadIdx.x == 0) {
        int nz = 0;
#pragma unroll
        for (int i = 1; i < 128; i += 2) nz |= ids32[i];
        g_ids_is64 = (nz == 0) ? 1 : 0;
    }
}

__device__ __forceinline__ long long load_id(const void* __restrict__ ids,
                                             int i, int is64) {
    if (is64) return ((const long long*)ids)[i];
    return (long long)((const int*)ids)[i];
}

__global__ __launch_bounds__(256)
void ngram_emb_mma_kernel(const void* __restrict__ ids,
                          const float* __restrict__ word,
                          const float* __restrict__ e0, const float* __restrict__ e1,
                          const float* __restrict__ e2, const float* __restrict__ e3,
                          const float* __restrict__ p0, const float* __restrict__ p1,
                          const float* __restrict__ p2, const float* __restrict__ p3,
                          float* __restrict__ out)
{
    extern __shared__ float smf[];
    uint32_t* smu = (uint32_t*)smf;

    const int tid  = threadIdx.x;
    const int wid  = tid >> 5;
    const int lane = tid & 31;
    const int m0   = blockIdx.y * BM;
    const int n0   = blockIdx.x * BN;
    const int is64 = g_ids_is64;

    const float* const embs[NEMB]  = {e0, e1, e2, e3};
    const float* const projs[NEMB] = {p0, p1, p2, p3};

    // ---- hashed ngram indices (EOS segment logic -> <=2 lookbacks) ----
    int* nid = (int*)(smf + NID_OFF);
    if (tid < BM) {
        const int p = m0 + tid;
        const int t = p & (S_LEN - 1);
        const long long id    = load_id(ids, p, is64);
        const long long prev1 = (t >= 1) ? load_id(ids, p - 1, is64) : EOS_ID;
        const long long prev2 = (t >= 2) ? load_id(ids, p - 2, is64) : EOS_ID;
        const bool ok1 = (t >= 1) && (prev1 != EOS_ID);
        const bool ok2 = (t >= 2) && (prev1 != EOS_ID) && (prev2 != EOS_ID);
        const long long s1 = ok1 ? prev1 : 0;
        const long long s2 = ok2 ? prev2 : 0;
#pragma unroll
        for (int e = 0; e < NEMB; e++) {
            const long long dim = 128000LL + 2 * e + 1;
            const long long m1  = VOCAB_L % dim;
            long long ng = id + s1 * m1;
            if (e >= 2) {
                const long long m2 = (m1 * VOCAB_L) % dim;
                ng += s2 * m2;
            }
            nid[e * BM + tid] = (int)(ng % dim);
        }
    }
    __syncthreads();

    // ---- producer mapping ----
    const int arow_l = (wid << 4) + (lane & 15);   // A row 0..127 (16 rows/warp)
    const int aq0    = (lane >> 4) * 4;            // float4 index base: 0 or 4
    const int brow_l = (wid << 5) + lane;          // B row 0..255 (32 rows/warp)

    float areg[4][4];   // staged A: 4 float4
    float breg[8][4];   // staged B: 8 float4

    // ---- compute mapping: 8 warps as 2(M) x 4(N), warp tile 64x64 ----
    const int wm = (wid >> 2) * 64;
    const int wn = (wid & 3) * 64;
    const int fr = lane >> 2;      // 0..7
    const int fc = lane & 3;       // 0..3
    const int sw = fc << 3;        // consumer swizzle term ((k&3)<<3)

    float acc[4][8][4];
#pragma unroll
    for (int i = 0; i < 4; i++)
#pragma unroll
        for (int j = 0; j < 8; j++)
#pragma unroll
            for (int q = 0; q < 4; q++) acc[i][j][q] = 0.0f;

#define LDG_CHUNK(c)                                                          \
    {                                                                         \
        const int e_ = (c) >> 4, k0_ = ((c) & 15) * BK;                       \
        const float* ar_ = embs[e_] +                                         \
            (size_t)nid[e_ * BM + arow_l] * EMBD + k0_;                       \
        _Pragma("unroll")                                                     \
        for (int i = 0; i < 4; i++)                                           \
            *(float4*)areg[i] = *(const float4*)(ar_ + (aq0 + i) * 4);        \
        const float* br_ = projs[e_] +                                        \
            (size_t)(n0 + brow_l) * EMBD + k0_;                               \
        _Pragma("unroll")                                                     \
        for (int i = 0; i < 8; i++)                                           \
            *(float4*)breg[i] = *(const float4*)(br_ + i * 4);                \
    }

#define STS_CHUNK(stage)                                                      \
    {                                                                         \
        uint32_t* A_ = smu + (stage) * A_F;                                   \
        uint32_t* B_ = smu + 2 * A_F + (stage) * B_F;                         \
        _Pragma("unroll")                                                     \
        for (int i = 0; i < 4; i++)                                           \
            _Pragma("unroll")                                                 \
            for (int j = 0; j < 4; j++)                                       \
                A_[((aq0 + i) * 4 + j) * BM + (arow_l ^ (j << 3))] =          \
                    cvt_tf32(areg[i][j]);                                     \
        _Pragma("unroll")                                                     \
        for (int i = 0; i < 8; i++)                                           \
            _Pragma("unroll")                                                 \
            for (int j = 0; j < 4; j++)                                       \
                B_[(i * 4 + j) * BN + (brow_l ^ (j << 3))] =                  \
                    cvt_tf32(breg[i][j]);                                     \
    }

#define COMPUTE_CHUNK(stage)                                                  \
    {                                                                         \
        const uint32_t* A_ = smu + (stage) * A_F;                             \
        const uint32_t* B_ = smu + 2 * A_F + (stage) * B_F;                   \
        _Pragma("unroll")                                                     \
        for (int ks = 0; ks < 4; ks++) {                                      \
            const int k_ = ks * 8 + fc;                                       \
            uint32_t af[4][4], bf[8][2];                                      \
            _Pragma("unroll")                                                 \
            for (int mt = 0; mt < 4; mt++) {                                  \
                const int m_ = wm + mt * 16 + fr;                             \
                af[mt][0] = A_[k_ * BM + (m_ ^ sw)];                          \
                af[mt][1] = A_[k_ * BM + ((m_ + 8) ^ sw)];                    \
                af[mt][2] = A_[(k_ + 4) * BM + (m_ ^ sw)];                    \
                af[mt][3] = A_[(k_ + 4) * BM + ((m_ + 8) ^ sw)];              \
            }                                                                 \
            _Pragma("unroll")                                                 \
            for (int nt = 0; nt < 8; nt++) {                                  \
                const int n_ = wn + nt * 8 + fr;                              \
                bf[nt][0] = B_[k_ * BN + (n_ ^ sw)];                          \
                bf[nt][1] = B_[(k_ + 4) * BN + (n_ ^ sw)];                    \
            }                                                                 \
            _Pragma("unroll")                                                 \
            for (int mt = 0; mt < 4; mt++)                                    \
                _Pragma("unroll")                                             \
                for (int nt = 0; nt < 8; nt++)                                \
                    mma_tf32(acc[mt][nt], af[mt], bf[nt]);                    \
        }                                                                     \
    }

    // ---- software-pipelined mainloop ----
    LDG_CHUNK(0);
    STS_CHUNK(0);
    __syncthreads();

    for (int c = 0; c < NCHUNK; c++) {
        const int st = c & 1;
        if (c + 1 < NCHUNK) LDG_CHUNK(c + 1);
        COMPUTE_CHUNK(st);
        if (c + 1 < NCHUNK) STS_CHUNK(st ^ 1);
        __syncthreads();
    }

    // ---- epilogue: + word_emb gather, x 1/5 ----
    const float inv = 1.0f / 5.0f;
#pragma unroll
    for (int mt = 0; mt < 4; mt++) {
#pragma unroll
        for (int half = 0; half < 2; half++) {
            const int mr = wm + mt * 16 + fr + half * 8;
            const int mg = m0 + mr;
            const long long tok = load_id(ids, mg, is64);
            const float* __restrict__ wr = word + (size_t)tok * HID;
            float* __restrict__ orow = out + (size_t)mg * HID;
#pragma unroll
            for (int nt = 0; nt < 8; nt++) {
                const int col = n0 + wn + nt * 8 + fc * 2;
                const float2 wv = *(const float2*)(wr + col);
                float2 o;
                o.x = (acc[mt][nt][half * 2 + 0] + wv.x) * inv;
                o.y = (acc[mt][nt][half * 2 + 1] + wv.y) * inv;
                *(float2*)(orow + col) = o;
            }
        }
    }
}

extern "C" void kernel_launch(void* const* d_in, const int* in_sizes, int n_in,
                              void* d_out, int out_size)
{
    // Identify inputs by element count:
    //   ids: 8192 (int32/int64 auto-detected)   word_emb: 65,536,000
    //   emb_e: 65,536,512 + 1024*e              proj_e: 1,048,576 (in order)
    const void* ids = nullptr;
    const float* word = nullptr;
    const float* emb[NEMB]  = {nullptr, nullptr, nullptr, nullptr};
    const float* proj[NEMB] = {nullptr, nullptr, nullptr, nullptr};
    int np = 0;
    int M = 8192;

    for (int i = 0; i < n_in; i++) {
        const long long sz = in_sizes[i];
        if (sz < 1000000) {
            ids = d_in[i];
            M = (int)sz;
        } else if (sz == 65536000LL) {
            word = (const float*)d_in[i];
        } else if (sz == 65536512LL) {
            emb[0] = (const float*)d_in[i];
        } else if (sz == 65537536LL) {
            emb[1] = (const float*)d_in[i];
        } else if (sz == 65538560LL) {
            emb[2] = (const float*)d_in[i];
        } else if (sz == 65539584LL) {
            emb[3] = (const float*)d_in[i];
        } else if (sz == 1048576LL && np < NEMB) {
            proj[np++] = (const float*)d_in[i];
        }
    }

    cudaFuncSetAttribute(ngram_emb_mma_kernel,
                         cudaFuncAttributeMaxDynamicSharedMemorySize, SMEM_BYTES);

    detect_ids_dtype_kernel<<<1, 32>>>((const int*)ids);

    dim3 grid(HID / BN, M / BM);   // (8, 64)
    ngram_emb_mma_kernel<<<grid, 256, SMEM_BYTES>>>(
        ids, word,
        emb[0], emb[1], emb[2], emb[3],
        proj[0], proj[1], proj[2], proj[3],
        (float*)d_out);
}

// round 6
// speedup vs baseline: 2.8043x; 1.5838x over previous
#include <cuda_runtime.h>
#include <cstdint>

// Problem constants
#define S_LEN   2048
#define HID     2048
#define EMBD    512
#define VOCAB_L 32000LL
#define EOS_ID  2LL
#define NEMB    4

// GEMM tiling
#define BM 128
#define BN 256
#define BK 32
#define NCHUNK 64                    // NEMB*EMBD/BK
#define NSTAGE 3
#define A_BYTES (BM * BK * 4)        // 16384
#define B_BYTES (BN * BK * 4)        // 32768
#define OFF_B   (NSTAGE * A_BYTES)
#define OFF_NID (OFF_B + NSTAGE * B_BYTES)
#define SMEM_BYTES (OFF_NID + NEMB * BM * 4)

__device__ int g_ids_is64;

__device__ __forceinline__ uint32_t s2u(const void* p) {
    uint32_t a;
    asm("{ .reg .u64 t; cvta.to.shared.u64 t, %1; cvt.u32.u64 %0, t; }"
        : "=r"(a) : "l"(p));
    return a;
}
__device__ __forceinline__ void cp16(uint32_t dst, const void* src) {
    asm volatile("cp.async.cg.shared.global [%0], [%1], 16;"
                 :: "r"(dst), "l"(src) : "memory");
}
__device__ __forceinline__ void mma_tf32(float* d, const uint32_t* a,
                                         const uint32_t* b) {
    asm volatile(
        "mma.sync.aligned.m16n8k8.row.col.f32.tf32.tf32.f32 "
        "{%0,%1,%2,%3}, {%4,%5,%6,%7}, {%8,%9}, {%0,%1,%2,%3};"
        : "+f"(d[0]), "+f"(d[1]), "+f"(d[2]), "+f"(d[3])
        : "r"(a[0]), "r"(a[1]), "r"(a[2]), "r"(a[3]), "r"(b[0]), "r"(b[1]));
}

// Detect int64 vs int32 ids transport (odd words all zero => int64 LE, ids<32000)
__global__ void detect_ids_dtype_kernel(const int* __restrict__ ids32) {
    if (threadIdx.x == 0) {
        int nz = 0;
#pragma unroll
        for (int i = 1; i < 128; i += 2) nz |= ids32[i];
        g_ids_is64 = (nz == 0) ? 1 : 0;
    }
}

__device__ __forceinline__ long long load_id(const void* __restrict__ ids,
                                             int i, int is64) {
    if (is64) return ((const long long*)ids)[i];
    return (long long)((const int*)ids)[i];
}

__global__ __launch_bounds__(256, 1)
void ngram_emb_mma_kernel(const void* __restrict__ ids,
                          const float* __restrict__ word,
                          const float* __restrict__ e0, const float* __restrict__ e1,
                          const float* __restrict__ e2, const float* __restrict__ e3,
                          const float* __restrict__ p0, const float* __restrict__ p1,
                          const float* __restrict__ p2, const float* __restrict__ p3,
                          float* __restrict__ out)
{
    extern __shared__ char smc[];
    const uint32_t smem_u = s2u(smc);

    const int tid  = threadIdx.x;
    const int wid  = tid >> 5;
    const int lane = tid & 31;
    const int m0   = blockIdx.y * BM;
    const int n0   = blockIdx.x * BN;
    const int is64 = g_ids_is64;

    const float* const embs[NEMB]  = {e0, e1, e2, e3};
    const float* const projs[NEMB] = {p0, p1, p2, p3};

    // ---- hashed ngram indices (EOS segment logic -> <=2 lookbacks) ----
    int* nid = (int*)(smc + OFF_NID);
    if (tid < BM) {
        const int p = m0 + tid;
        const int t = p & (S_LEN - 1);
        const long long id    = load_id(ids, p, is64);
        const long long prev1 = (t >= 1) ? load_id(ids, p - 1, is64) : EOS_ID;
        const long long prev2 = (t >= 2) ? load_id(ids, p - 2, is64) : EOS_ID;
        const bool ok1 = (t >= 1) && (prev1 != EOS_ID);
        const bool ok2 = (t >= 2) && (prev1 != EOS_ID) && (prev2 != EOS_ID);
        const long long s1 = ok1 ? prev1 : 0;
        const long long s2 = ok2 ? prev2 : 0;
#pragma unroll
        for (int e = 0; e < NEMB; e++) {
            const long long dim = 128000LL + 2 * e + 1;
            const long long m1  = VOCAB_L % dim;
            long long ng = id + s1 * m1;
            if (e >= 2) {
                const long long m2 = (m1 * VOCAB_L) % dim;
                ng += s2 * m2;
            }
            nid[e * BM + tid] = (int)(ng % dim);
        }
    }
    __syncthreads();

    // ---- producer mapping: thread -> (row = tid/2, 4 of 8 16B groups) ----
    const int prow = tid >> 1;            // 0..127
    const int pgb  = (tid & 1) * 4;       // group base: 0 or 4

    // ---- compute mapping: 8 warps as 2(M) x 4(N), warp tile 64x64 ----
    const int wm = (wid >> 2) * 64;
    const int wn = (wid & 3) * 64;
    const int fr = lane >> 2;             // 0..7
    const int fc = lane & 3;              // 0..3

    float acc[4][8][4];
#pragma unroll
    for (int i = 0; i < 4; i++)
#pragma unroll
        for (int j = 0; j < 8; j++)
#pragma unroll
            for (int q = 0; q < 4; q++) acc[i][j][q] = 0.0f;

    // SMEM layout: A_s[row][k] row-major, 128B/row, group swizzle g^=(row&7).
#define LDGSTS_CHUNK(c, stage)                                                \
    {                                                                         \
        const int e_ = (c) >> 4, k0_ = ((c) & 15) * BK;                       \
        const float* ar_ = embs[e_] +                                         \
            (size_t)nid[e_ * BM + prow] * EMBD + k0_;                         \
        const uint32_t abase_ = smem_u + (stage) * A_BYTES + prow * 128;      \
        _Pragma("unroll")                                                     \
        for (int i = 0; i < 4; i++) {                                         \
            const int g_ = pgb + i;                                           \
            cp16(abase_ + ((g_ ^ (prow & 7)) << 4), ar_ + g_ * 4);            \
        }                                                                     \
        _Pragma("unroll")                                                     \
        for (int rb = 0; rb < 2; rb++) {                                      \
            const int row_ = rb * 128 + prow;                                 \
            const float* br_ = projs[e_] +                                    \
                (size_t)(n0 + row_) * EMBD + k0_;                             \
            const uint32_t bbase_ = smem_u + OFF_B + (stage) * B_BYTES +      \
                                    row_ * 128;                               \
            _Pragma("unroll")                                                 \
            for (int i = 0; i < 4; i++) {                                     \
                const int g_ = pgb + i;                                       \
                cp16(bbase_ + ((g_ ^ (row_ & 7)) << 4), br_ + g_ * 4);        \
            }                                                                 \
        }                                                                     \
        asm volatile("cp.async.commit_group;" ::: "memory");                  \
    }

#define COMPUTE_CHUNK(stage)                                                  \
    {                                                                         \
        const char* A_ = smc + (stage) * A_BYTES;                             \
        const char* B_ = smc + OFF_B + (stage) * B_BYTES;                     \
        _Pragma("unroll")                                                     \
        for (int ks = 0; ks < 4; ks++) {                                      \
            const int g0 = 2 * ks, g1 = 2 * ks + 1;                           \
            uint32_t af[4][4], bf[8][2];                                      \
            _Pragma("unroll")                                                 \
            for (int mt = 0; mt < 4; mt++) {                                  \
                const int m_ = wm + mt * 16 + fr;                             \
                const int sw_ = m_ & 7;                                       \
                const char* r0_ = A_ + m_ * 128 + fc * 4;                     \
                const char* r1_ = A_ + (m_ + 8) * 128 + fc * 4;               \
                af[mt][0] = *(const uint32_t*)(r0_ + ((g0 ^ sw_) << 4));      \
                af[mt][1] = *(const uint32_t*)(r1_ + ((g0 ^ sw_) << 4));      \
                af[mt][2] = *(const uint32_t*)(r0_ + ((g1 ^ sw_) << 4));      \
                af[mt][3] = *(const uint32_t*)(r1_ + ((g1 ^ sw_) << 4));      \
            }                                                                 \
            _Pragma("unroll")                                                 \
            for (int nt = 0; nt < 8; nt++) {                                  \
                const int n_ = wn + nt * 8 + fr;                              \
                const int sw_ = n_ & 7;                                       \
                const char* rn_ = B_ + n_ * 128 + fc * 4;                     \
                bf[nt][0] = *(const uint32_t*)(rn_ + ((g0 ^ sw_) << 4));      \
                bf[nt][1] = *(const uint32_t*)(rn_ + ((g1 ^ sw_) << 4));      \
            }                                                                 \
            _Pragma("unroll")                                                 \
            for (int mt = 0; mt < 4; mt++)                                    \
                _Pragma("unroll")                                             \
                for (int nt = 0; nt < 8; nt++)                                \
                    mma_tf32(acc[mt][nt], af[mt], bf[nt]);                    \
        }                                                                     \
    }

    // ---- pipelined mainloop: 3-stage cp.async ----
    LDGSTS_CHUNK(0, 0);
    LDGSTS_CHUNK(1, 1);
    LDGSTS_CHUNK(2, 2);

    for (int c = 0; c < NCHUNK; c++) {
        const int st = c % NSTAGE;
        if (c + NSTAGE < NCHUNK) {
            asm volatile("cp.async.wait_group 2;" ::: "memory");
        } else {
            asm volatile("cp.async.wait_group 0;" ::: "memory");
        }
        __syncthreads();
        COMPUTE_CHUNK(st);
        __syncthreads();
        if (c + NSTAGE < NCHUNK) LDGSTS_CHUNK(c + NSTAGE, st);
    }

    // ---- epilogue: + word_emb gather, x 1/5 ----
    const float inv = 1.0f / 5.0f;
#pragma unroll
    for (int mt = 0; mt < 4; mt++) {
#pragma unroll
        for (int half = 0; half < 2; half++) {
            const int mr = wm + mt * 16 + fr + half * 8;
            const int mg = m0 + mr;
            const long long tok = load_id(ids, mg, is64);
            const float* __restrict__ wr = word + (size_t)tok * HID;
            float* __restrict__ orow = out + (size_t)mg * HID;
#pragma unroll
            for (int nt = 0; nt < 8; nt++) {
                const int col = n0 + wn + nt * 8 + fc * 2;
                const float2 wv = *(const float2*)(wr + col);
                float2 o;
                o.x = (acc[mt][nt][half * 2 + 0] + wv.x) * inv;
                o.y = (acc[mt][nt][half * 2 + 1] + wv.y) * inv;
                *(float2*)(orow + col) = o;
            }
        }
    }
}

extern "C" void kernel_launch(void* const* d_in, const int* in_sizes, int n_in,
                              void* d_out, int out_size)
{
    // Identify inputs by element count:
    //   ids: 8192 (int32/int64 auto-detected)   word_emb: 65,536,000
    //   emb_e: 65,536,512 + 1024*e              proj_e: 1,048,576 (in order)
    const void* ids = nullptr;
    const float* word = nullptr;
    const float* emb[NEMB]  = {nullptr, nullptr, nullptr, nullptr};
    const float* proj[NEMB] = {nullptr, nullptr, nullptr, nullptr};
    int np = 0;
    int M = 8192;

    for (int i = 0; i < n_in; i++) {
        const long long sz = in_sizes[i];
        if (sz < 1000000) {
            ids = d_in[i];
            M = (int)sz;
        } else if (sz == 65536000LL) {
            word = (const float*)d_in[i];
        } else if (sz == 65536512LL) {
            emb[0] = (const float*)d_in[i];
        } else if (sz == 65537536LL) {
            emb[1] = (const float*)d_in[i];
        } else if (sz == 65538560LL) {
            emb[2] = (const float*)d_in[i];
        } else if (sz == 65539584LL) {
            emb[3] = (const float*)d_in[i];
        } else if (sz == 1048576LL && np < NEMB) {
            proj[np++] = (const float*)d_in[i];
        }
    }

    cudaFuncSetAttribute(ngram_emb_mma_kernel,
                         cudaFuncAttributeMaxDynamicSharedMemorySize, SMEM_BYTES);

    detect_ids_dtype_kernel<<<1, 32>>>((const int*)ids);

    dim3 grid(HID / BN, M / BM);   // (8, 64)
    ngram_emb_mma_kernel<<<grid, 256, SMEM_BYTES>>>(
        ids, word,
        emb[0], emb[1], emb[2], emb[3],
        proj[0], proj[1], proj[2], proj[3],
        (float*)d_out);
}